// round 1
// baseline (speedup 1.0000x reference)
#include <cuda_runtime.h>

// Problem constants
#define B_   32
#define S_   512
#define D_   768
#define H_   12
#define HD_  64
#define M_   (B_ * S_)       // 16384 rows
#define NQKV (3 * D_)        // 2304

// Scratch (device globals per allocation rules)
__device__ float g_qkv[(size_t)M_ * NQKV];   // [B*S, 3D] fused qkv output
__device__ float g_att[(size_t)M_ * D_];     // [B*S, D]  attention output

// ---------------------------------------------------------------------------
// SGEMM with bias: C[M,N] = A[M,K] @ W[N,K]^T + bias[N]
// Block tile 128x128, K-tile 8, 256 threads, 8x8 per thread.
// All relevant dims divide tiles exactly (M=16384, N in {2304,768}, K=768).
// ---------------------------------------------------------------------------
__global__ __launch_bounds__(256) void sgemm_bias_kernel(
    const float* __restrict__ A, const float* __restrict__ W,
    const float* __restrict__ bias, float* __restrict__ C,
    int N, int K)
{
    __shared__ float As[8][128];
    __shared__ float Ws[8][128];

    const int tid = threadIdx.x;
    const int tx  = tid & 15;        // 0..15 -> col group
    const int ty  = tid >> 4;        // 0..15 -> row group
    const int bm  = blockIdx.y * 128;
    const int bn  = blockIdx.x * 128;

    float acc[8][8];
#pragma unroll
    for (int i = 0; i < 8; i++)
#pragma unroll
        for (int j = 0; j < 8; j++) acc[i][j] = 0.f;

    // Load mapping: each thread fetches one float4 of A-tile and W-tile
    const int lrow = tid >> 1;           // 0..127
    const int lc   = (tid & 1) * 4;      // 0 or 4
    const float* Ap = A + (size_t)(bm + lrow) * K + lc;
    const float* Wp = W + (size_t)(bn + lrow) * K + lc;

    for (int k0 = 0; k0 < K; k0 += 8) {
        float4 av = *(const float4*)(Ap + k0);
        float4 wv = *(const float4*)(Wp + k0);

        __syncthreads();   // previous compute done before overwrite
        As[lc + 0][lrow] = av.x;  As[lc + 1][lrow] = av.y;
        As[lc + 2][lrow] = av.z;  As[lc + 3][lrow] = av.w;
        Ws[lc + 0][lrow] = wv.x;  Ws[lc + 1][lrow] = wv.y;
        Ws[lc + 2][lrow] = wv.z;  Ws[lc + 3][lrow] = wv.w;
        __syncthreads();

#pragma unroll
        for (int k = 0; k < 8; k++) {
            float a[8], b[8];
            *(float4*)&a[0] = *(const float4*)&As[k][ty * 8];
            *(float4*)&a[4] = *(const float4*)&As[k][ty * 8 + 4];
            *(float4*)&b[0] = *(const float4*)&Ws[k][tx * 8];
            *(float4*)&b[4] = *(const float4*)&Ws[k][tx * 8 + 4];
#pragma unroll
            for (int i = 0; i < 8; i++)
#pragma unroll
                for (int j = 0; j < 8; j++)
                    acc[i][j] = fmaf(a[i], b[j], acc[i][j]);
        }
    }

    // Epilogue: add bias, store float4
#pragma unroll
    for (int i = 0; i < 8; i++) {
        const size_t row = (size_t)(bm + ty * 8 + i);
#pragma unroll
        for (int j = 0; j < 8; j += 4) {
            const int col = bn + tx * 8 + j;
            float4 bv = *(const float4*)&bias[col];
            float4 o;
            o.x = acc[i][j + 0] + bv.x;
            o.y = acc[i][j + 1] + bv.y;
            o.z = acc[i][j + 2] + bv.z;
            o.w = acc[i][j + 3] + bv.w;
            *(float4*)&C[row * N + col] = o;
        }
    }
}

// ---------------------------------------------------------------------------
// Flash attention: grid (S/64, H, B), block 128 threads.
// Thread t handles q-row r = t/2, HD-half d0 = (t&1)*32.
// K/V 64x64 tiles staged in smem; scores + online softmax in registers.
// q/k/v live interleaved in g_qkv: row base (b*S+s)*2304, offsets 0/768/1536,
// head slice h*64.
// ---------------------------------------------------------------------------
__global__ __launch_bounds__(128) void attn_kernel()
{
    __shared__ float Kt[64][64];
    __shared__ float Vt[64][64];

    const int t  = threadIdx.x;
    const int r  = t >> 1;
    const int d0 = (t & 1) * 32;
    const int qt = blockIdx.x;    // q tile (0..7)
    const int h  = blockIdx.y;
    const int b  = blockIdx.z;
    const float scale = 0.125f;   // 1/sqrt(64)

    // Load this thread's half of the q row into registers
    const size_t qbase = ((size_t)b * S_ + qt * 64 + r) * NQKV + h * HD_ + d0;
    float q[32];
#pragma unroll
    for (int i = 0; i < 8; i++)
        *(float4*)&q[i * 4] = *(const float4*)&g_qkv[qbase + i * 4];

    float o[32];
#pragma unroll
    for (int i = 0; i < 32; i++) o[i] = 0.f;
    float m = -1e30f, l = 0.f;

    for (int j = 0; j < 8; j++) {
        // Stage K/V tiles (coalesced: 16 consecutive lanes cover one 64B half-row)
#pragma unroll
        for (int i = 0; i < 8; i++) {
            const int linear = i * 128 + t;        // float4 index 0..1023
            const int c  = linear >> 4;
            const int dd = (linear & 15) * 4;
            const size_t src = ((size_t)b * S_ + j * 64 + c) * NQKV + D_ + h * HD_ + dd;
            *(float4*)&Kt[c][dd] = *(const float4*)&g_qkv[src];        // K
            *(float4*)&Vt[c][dd] = *(const float4*)&g_qkv[src + D_];   // V
        }
        __syncthreads();

        // Partial dots over this thread's 32 dims
        float s[64];
#pragma unroll
        for (int c = 0; c < 64; c++) {
            float acc0 = 0.f;
#pragma unroll
            for (int i = 0; i < 8; i++) {
                float4 kv = *(const float4*)&Kt[c][d0 + i * 4];
                acc0 = fmaf(q[i * 4 + 0], kv.x, acc0);
                acc0 = fmaf(q[i * 4 + 1], kv.y, acc0);
                acc0 = fmaf(q[i * 4 + 2], kv.z, acc0);
                acc0 = fmaf(q[i * 4 + 3], kv.w, acc0);
            }
            s[c] = acc0;
        }
        // Combine halves (lanes 2r / 2r+1 are adjacent in the same warp)
#pragma unroll
        for (int c = 0; c < 64; c++)
            s[c] = (s[c] + __shfl_xor_sync(0xffffffffu, s[c], 1)) * scale;

        // Online softmax update
        float mt = m;
#pragma unroll
        for (int c = 0; c < 64; c++) mt = fmaxf(mt, s[c]);
        const float corr = __expf(m - mt);
        m = mt;
        l *= corr;
#pragma unroll
        for (int i = 0; i < 32; i++) o[i] *= corr;

#pragma unroll
        for (int c = 0; c < 64; c++) {
            const float p = __expf(s[c] - m);
            l += p;
#pragma unroll
            for (int i = 0; i < 8; i++) {
                float4 vv = *(const float4*)&Vt[c][d0 + i * 4];
                o[i * 4 + 0] = fmaf(p, vv.x, o[i * 4 + 0]);
                o[i * 4 + 1] = fmaf(p, vv.y, o[i * 4 + 1]);
                o[i * 4 + 2] = fmaf(p, vv.z, o[i * 4 + 2]);
                o[i * 4 + 3] = fmaf(p, vv.w, o[i * 4 + 3]);
            }
        }
        __syncthreads();   // reads done before next tile's stores
    }

    const float inv = 1.f / l;
    const size_t obase = ((size_t)b * S_ + qt * 64 + r) * D_ + h * HD_ + d0;
#pragma unroll
    for (int i = 0; i < 8; i++) {
        float4 ov;
        ov.x = o[i * 4 + 0] * inv;
        ov.y = o[i * 4 + 1] * inv;
        ov.z = o[i * 4 + 2] * inv;
        ov.w = o[i * 4 + 3] * inv;
        *(float4*)&g_att[obase + i * 4] = ov;
    }
}

// ---------------------------------------------------------------------------
extern "C" void kernel_launch(void* const* d_in, const int* in_sizes, int n_in,
                              void* d_out, int out_size)
{
    const float* x      = (const float*)d_in[0];
    const float* qkv_w  = (const float*)d_in[1];
    const float* qkv_b  = (const float*)d_in[2];
    const float* proj_w = (const float*)d_in[3];
    const float* proj_b = (const float*)d_in[4];
    float* out = (float*)d_out;

    float *qkv_ptr, *att_ptr;
    cudaGetSymbolAddress((void**)&qkv_ptr, g_qkv);
    cudaGetSymbolAddress((void**)&att_ptr, g_att);

    // 1) fused QKV projection: [16384,768] @ [2304,768]^T + b
    dim3 g1(NQKV / 128, M_ / 128);
    sgemm_bias_kernel<<<g1, 256>>>(x, qkv_w, qkv_b, qkv_ptr, NQKV, D_);

    // 2) flash attention
    dim3 g2(S_ / 64, H_, B_);
    attn_kernel<<<g2, 128>>>();

    // 3) output projection: [16384,768] @ [768,768]^T + b
    dim3 g3(D_ / 128, M_ / 128);
    sgemm_bias_kernel<<<g3, 256>>>(att_ptr, proj_w, proj_b, out, D_, D_);
}

// round 3
// speedup vs baseline: 1.4712x; 1.4712x over previous
#include <cuda_runtime.h>
#include <cuda_bf16.h>
#include <cstdint>

// Problem constants
#define B_   32
#define S_   512
#define D_   768
#define H_   12
#define HD_  64
#define M_   (B_ * S_)       // 16384 rows
#define NQKV (3 * D_)        // 2304

// ---------------------------------------------------------------------------
// Scratch (device globals per allocation rules)
// ---------------------------------------------------------------------------
__device__ float g_qkv[(size_t)M_ * NQKV];          // [B*S, 3D] fused qkv output (fp32)
__device__ float g_att[(size_t)M_ * D_];            // [B*S, D]  attention output (fp32)
__device__ __nv_bfloat16 g_xh[(size_t)M_ * D_];     // x split hi
__device__ __nv_bfloat16 g_xl[(size_t)M_ * D_];     // x split lo
__device__ __nv_bfloat16 g_ah[(size_t)M_ * D_];     // att out split hi
__device__ __nv_bfloat16 g_al[(size_t)M_ * D_];     // att out split lo
__device__ __nv_bfloat16 g_qwh[(size_t)NQKV * D_];  // qkv_w hi
__device__ __nv_bfloat16 g_qwl[(size_t)NQKV * D_];  // qkv_w lo
__device__ __nv_bfloat16 g_pwh[(size_t)D_ * D_];    // proj_w hi
__device__ __nv_bfloat16 g_pwl[(size_t)D_ * D_];    // proj_w lo

// ---------------------------------------------------------------------------
// Helpers
// ---------------------------------------------------------------------------
__device__ __forceinline__ uint32_t smem_u32(const void* p) {
    uint32_t a;
    asm("{ .reg .u64 t; cvta.to.shared.u64 t, %1; cvt.u32.u64 %0, t; }" : "=r"(a) : "l"(p));
    return a;
}
#define CP16(dst, src) \
    asm volatile("cp.async.cg.shared.global [%0], [%1], 16;\n" :: "r"(dst), "l"(src))
#define CP_COMMIT()  asm volatile("cp.async.commit_group;\n" ::: "memory")
#define CP_WAIT1()   asm volatile("cp.async.wait_group 1;\n" ::: "memory")

#define LDSM4(R, addr) \
    asm volatile("ldmatrix.sync.aligned.m8n8.x4.shared.b16 {%0,%1,%2,%3}, [%4];" \
                 : "=r"((R)[0]), "=r"((R)[1]), "=r"((R)[2]), "=r"((R)[3]) : "r"(addr))

#define MMA16816(D, A, b0v, b1v) \
    asm volatile("mma.sync.aligned.m16n8k16.row.col.f32.bf16.bf16.f32 " \
                 "{%0,%1,%2,%3},{%4,%5,%6,%7},{%8,%9},{%0,%1,%2,%3};" \
                 : "+f"((D)[0]), "+f"((D)[1]), "+f"((D)[2]), "+f"((D)[3]) \
                 : "r"((A)[0]), "r"((A)[1]), "r"((A)[2]), "r"((A)[3]), \
                   "r"(b0v), "r"(b1v))

// ---------------------------------------------------------------------------
// Split fp32 -> bf16 hi/lo  (vectorized by 4)
// ---------------------------------------------------------------------------
__global__ __launch_bounds__(256) void split_kernel(
    const float* __restrict__ src, __nv_bfloat16* __restrict__ hi,
    __nv_bfloat16* __restrict__ lo, int n4)
{
    int i = blockIdx.x * blockDim.x + threadIdx.x;
    if (i >= n4) return;
    float4 v = ((const float4*)src)[i];
    union { __nv_bfloat16 b[4]; uint2 u; } uh, ul;
    float f[4] = {v.x, v.y, v.z, v.w};
#pragma unroll
    for (int j = 0; j < 4; j++) {
        __nv_bfloat16 h = __float2bfloat16_rn(f[j]);
        uh.b[j] = h;
        ul.b[j] = __float2bfloat16_rn(f[j] - __bfloat162float(h));
    }
    ((uint2*)hi)[i] = uh.u;
    ((uint2*)lo)[i] = ul.u;
}

// ---------------------------------------------------------------------------
// bf16x3 tensor-core GEMM (mma.sync): C[M,N] = (Ah+Al)@(Wh+Wl)^T + bias
// CTA tile 128x128, K-tile 32, 3-stage cp.async pipeline, 256 threads.
// Warp grid 4(M) x 2(N): each warp 32x64 via m16n8k16 fragments.
// SMEM: 4 tiles/stage (Ah, Al, Wh, Wl), rows padded to 80B (conflict-free
// ldmatrix: bank-group = (5r + c) mod 8, distinct for r=0..7).
// ---------------------------------------------------------------------------
#define KT        32
#define RSTRIDE   80                      // bytes per padded row (40 bf16)
#define TILE_B    (128 * RSTRIDE)         // 10240
#define STAGE_B   (4 * TILE_B)            // 40960
#define NSTAGE    3
#define GEMM_SMEM (NSTAGE * STAGE_B)      // 122880

__global__ __launch_bounds__(256, 1) void gemm_mma_kernel(
    const __nv_bfloat16* __restrict__ Ah, const __nv_bfloat16* __restrict__ Al,
    const __nv_bfloat16* __restrict__ Wh, const __nv_bfloat16* __restrict__ Wl,
    const float* __restrict__ bias, float* __restrict__ C, int N, int K)
{
    extern __shared__ char smem[];
    const uint32_t sb = smem_u32(smem);
    const int tid  = threadIdx.x;
    const int wid  = tid >> 5;
    const int lane = tid & 31;
    const int wm   = wid & 3;        // 0..3 -> 32-row slice
    const int wn   = wid >> 2;       // 0..1 -> 64-col slice
    const int m0   = blockIdx.y * 128;
    const int n0   = blockIdx.x * 128;

    float acc[2][8][4];
#pragma unroll
    for (int a = 0; a < 2; a++)
#pragma unroll
        for (int b = 0; b < 8; b++)
#pragma unroll
            for (int c = 0; c < 4; c++) acc[a][b][c] = 0.f;

    const int nkc = K / KT;

    // ---- async stage loader: 2048 16B-chunks, 8 per thread ----
    auto issue_stage = [&](int kc, int s) {
        const int k0 = kc * KT;
        const uint32_t sbase = sb + s * STAGE_B;
#pragma unroll
        for (int it = 0; it < 8; it++) {
            const int lin  = it * 256 + tid;      // 0..2047
            const int tile = lin >> 9;            // 0..3
            const int idx  = lin & 511;
            const int r    = idx >> 2;
            const int c    = idx & 3;
            const uint32_t dst = sbase + tile * TILE_B + r * RSTRIDE + c * 16;
            const __nv_bfloat16* src;
            if (tile == 0)      src = Ah + (size_t)(m0 + r) * K + k0 + c * 8;
            else if (tile == 1) src = Al + (size_t)(m0 + r) * K + k0 + c * 8;
            else if (tile == 2) src = Wh + (size_t)(n0 + r) * K + k0 + c * 8;
            else                src = Wl + (size_t)(n0 + r) * K + k0 + c * 8;
            CP16(dst, src);
        }
        CP_COMMIT();
    };

    issue_stage(0, 0);
    if (nkc > 1) issue_stage(1, 1); else CP_COMMIT();

    // per-lane ldmatrix address components (constant across k-loop)
    const int arow_base = wm * 32 + (lane & 15);          // + mt*16
    const int aco       = (lane >> 4);                    // chunk offset 0/1
    const int brow_base = wn * 64 + (((lane >> 4) << 3) | (lane & 7));  // + ng*16
    const int bco       = ((lane >> 3) & 1);

    for (int kc = 0; kc < nkc; kc++) {
        const int s = kc % NSTAGE;
        CP_WAIT1();                 // stage kc resident
        __syncthreads();

        // prefetch stage kc+2 into the buffer freed by iter kc-1
        if (kc + 2 < nkc) issue_stage(kc + 2, (kc + 2) % NSTAGE);
        else CP_COMMIT();

        const uint32_t sbase = sb + s * STAGE_B;
#pragma unroll
        for (int j = 0; j < 2; j++) {           // two k16 steps per stage
            uint32_t ah[2][4], al[2][4], bh[4][4], bl[4][4];
#pragma unroll
            for (int mt = 0; mt < 2; mt++) {
                const uint32_t ad = sbase + (arow_base + mt * 16) * RSTRIDE
                                  + (2 * j + aco) * 16;
                LDSM4(ah[mt], ad);
                LDSM4(al[mt], ad + TILE_B);
            }
#pragma unroll
            for (int ng = 0; ng < 4; ng++) {
                const uint32_t bd = sbase + 2 * TILE_B
                                  + (brow_base + ng * 16) * RSTRIDE
                                  + (2 * j + bco) * 16;
                LDSM4(bh[ng], bd);
                LDSM4(bl[ng], bd + TILE_B);
            }
#pragma unroll
            for (int mt = 0; mt < 2; mt++)
#pragma unroll
                for (int ng = 0; ng < 4; ng++)
#pragma unroll
                    for (int p = 0; p < 2; p++) {
                        float* d = acc[mt][ng * 2 + p];
                        MMA16816(d, ah[mt], bh[ng][2 * p], bh[ng][2 * p + 1]);
                        MMA16816(d, ah[mt], bl[ng][2 * p], bl[ng][2 * p + 1]);
                        MMA16816(d, al[mt], bh[ng][2 * p], bh[ng][2 * p + 1]);
                    }
        }
        __syncthreads();
    }

    // ---- epilogue: bias add + fp32 store ----
    const int g = lane >> 2;
    const int t = lane & 3;
#pragma unroll
    for (int mt = 0; mt < 2; mt++) {
        const int row0 = m0 + wm * 32 + mt * 16 + g;
#pragma unroll
        for (int nt = 0; nt < 8; nt++) {
            const int col = n0 + wn * 64 + nt * 8 + t * 2;
            const float2 bv = *(const float2*)&bias[col];
            float2 v0, v1;
            v0.x = acc[mt][nt][0] + bv.x;  v0.y = acc[mt][nt][1] + bv.y;
            v1.x = acc[mt][nt][2] + bv.x;  v1.y = acc[mt][nt][3] + bv.y;
            *(float2*)&C[(size_t)row0 * N + col]       = v0;
            *(float2*)&C[(size_t)(row0 + 8) * N + col] = v1;
        }
    }
}

// ---------------------------------------------------------------------------
// Flash attention (fp32 FMA, unchanged): grid (S/64, H, B), block 128.
// ---------------------------------------------------------------------------
__global__ __launch_bounds__(128) void attn_kernel()
{
    __shared__ float Kt[64][64];
    __shared__ float Vt[64][64];

    const int t  = threadIdx.x;
    const int r  = t >> 1;
    const int d0 = (t & 1) * 32;
    const int qt = blockIdx.x;
    const int h  = blockIdx.y;
    const int b  = blockIdx.z;
    const float scale = 0.125f;

    const size_t qbase = ((size_t)b * S_ + qt * 64 + r) * NQKV + h * HD_ + d0;
    float q[32];
#pragma unroll
    for (int i = 0; i < 8; i++)
        *(float4*)&q[i * 4] = *(const float4*)&g_qkv[qbase + i * 4];

    float o[32];
#pragma unroll
    for (int i = 0; i < 32; i++) o[i] = 0.f;
    float m = -1e30f, l = 0.f;

    for (int j = 0; j < 8; j++) {
#pragma unroll
        for (int i = 0; i < 8; i++) {
            const int linear = i * 128 + t;
            const int c  = linear >> 4;
            const int dd = (linear & 15) * 4;
            const size_t src = ((size_t)b * S_ + j * 64 + c) * NQKV + D_ + h * HD_ + dd;
            *(float4*)&Kt[c][dd] = *(const float4*)&g_qkv[src];
            *(float4*)&Vt[c][dd] = *(const float4*)&g_qkv[src + D_];
        }
        __syncthreads();

        float s[64];
#pragma unroll
        for (int c = 0; c < 64; c++) {
            float acc0 = 0.f;
#pragma unroll
            for (int i = 0; i < 8; i++) {
                float4 kv = *(const float4*)&Kt[c][d0 + i * 4];
                acc0 = fmaf(q[i * 4 + 0], kv.x, acc0);
                acc0 = fmaf(q[i * 4 + 1], kv.y, acc0);
                acc0 = fmaf(q[i * 4 + 2], kv.z, acc0);
                acc0 = fmaf(q[i * 4 + 3], kv.w, acc0);
            }
            s[c] = acc0;
        }
#pragma unroll
        for (int c = 0; c < 64; c++)
            s[c] = (s[c] + __shfl_xor_sync(0xffffffffu, s[c], 1)) * scale;

        float mt = m;
#pragma unroll
        for (int c = 0; c < 64; c++) mt = fmaxf(mt, s[c]);
        const float corr = __expf(m - mt);
        m = mt;
        l *= corr;
#pragma unroll
        for (int i = 0; i < 32; i++) o[i] *= corr;

#pragma unroll
        for (int c = 0; c < 64; c++) {
            const float p = __expf(s[c] - m);
            l += p;
#pragma unroll
            for (int i = 0; i < 8; i++) {
                float4 vv = *(const float4*)&Vt[c][d0 + i * 4];
                o[i * 4 + 0] = fmaf(p, vv.x, o[i * 4 + 0]);
                o[i * 4 + 1] = fmaf(p, vv.y, o[i * 4 + 1]);
                o[i * 4 + 2] = fmaf(p, vv.z, o[i * 4 + 2]);
                o[i * 4 + 3] = fmaf(p, vv.w, o[i * 4 + 3]);
            }
        }
        __syncthreads();
    }

    const float inv = 1.f / l;
    const size_t obase = ((size_t)b * S_ + qt * 64 + r) * D_ + h * HD_ + d0;
#pragma unroll
    for (int i = 0; i < 8; i++) {
        float4 ov;
        ov.x = o[i * 4 + 0] * inv;
        ov.y = o[i * 4 + 1] * inv;
        ov.z = o[i * 4 + 2] * inv;
        ov.w = o[i * 4 + 3] * inv;
        *(float4*)&g_att[obase + i * 4] = ov;
    }
}

// ---------------------------------------------------------------------------
extern "C" void kernel_launch(void* const* d_in, const int* in_sizes, int n_in,
                              void* d_out, int out_size)
{
    const float* x      = (const float*)d_in[0];
    const float* qkv_w  = (const float*)d_in[1];
    const float* qkv_b  = (const float*)d_in[2];
    const float* proj_w = (const float*)d_in[3];
    const float* proj_b = (const float*)d_in[4];
    float* out = (float*)d_out;

    float *qkv_ptr, *att_ptr;
    __nv_bfloat16 *xh, *xl, *ah, *al, *qwh, *qwl, *pwh, *pwl;
    cudaGetSymbolAddress((void**)&qkv_ptr, g_qkv);
    cudaGetSymbolAddress((void**)&att_ptr, g_att);
    cudaGetSymbolAddress((void**)&xh, g_xh);
    cudaGetSymbolAddress((void**)&xl, g_xl);
    cudaGetSymbolAddress((void**)&ah, g_ah);
    cudaGetSymbolAddress((void**)&al, g_al);
    cudaGetSymbolAddress((void**)&qwh, g_qwh);
    cudaGetSymbolAddress((void**)&qwl, g_qwl);
    cudaGetSymbolAddress((void**)&pwh, g_pwh);
    cudaGetSymbolAddress((void**)&pwl, g_pwl);

    cudaFuncSetAttribute(gemm_mma_kernel,
                         cudaFuncAttributeMaxDynamicSharedMemorySize, GEMM_SMEM);

    // 1) split inputs to bf16 hi/lo
    {
        int n4 = (M_ * D_) / 4;
        split_kernel<<<(n4 + 255) / 256, 256>>>(x, xh, xl, n4);
        n4 = (NQKV * D_) / 4;
        split_kernel<<<(n4 + 255) / 256, 256>>>(qkv_w, qwh, qwl, n4);
        n4 = (D_ * D_) / 4;
        split_kernel<<<(n4 + 255) / 256, 256>>>(proj_w, pwh, pwl, n4);
    }

    // 2) QKV projection (tensor cores): [16384,768] @ [2304,768]^T + b
    {
        dim3 g(NQKV / 128, M_ / 128);
        gemm_mma_kernel<<<g, 256, GEMM_SMEM>>>(xh, xl, qwh, qwl, qkv_b, qkv_ptr,
                                               NQKV, D_);
    }

    // 3) flash attention (fp32)
    {
        dim3 g(S_ / 64, H_, B_);
        attn_kernel<<<g, 128>>>();
    }

    // 4) split attention output, then output projection
    {
        int n4 = (M_ * D_) / 4;
        split_kernel<<<(n4 + 255) / 256, 256>>>(att_ptr, ah, al, n4);
        dim3 g(D_ / 128, M_ / 128);
        gemm_mma_kernel<<<g, 256, GEMM_SMEM>>>(ah, al, pwh, pwl, proj_b, out,
                                               D_, D_);
    }
}

// round 6
// speedup vs baseline: 3.1519x; 2.1424x over previous
#include <cuda_runtime.h>
#include <cuda_bf16.h>
#include <cstdint>

// Problem constants
#define B_   32
#define S_   512
#define D_   768
#define H_   12
#define HD_  64
#define M_   (B_ * S_)       // 16384 rows
#define NQKV (3 * D_)        // 2304

// ---------------------------------------------------------------------------
// Scratch (device globals per allocation rules)
// ---------------------------------------------------------------------------
__device__ __nv_bfloat16 g_xh[(size_t)M_ * D_];     // x split hi
__device__ __nv_bfloat16 g_xl[(size_t)M_ * D_];     // x split lo
__device__ __nv_bfloat16 g_ah[(size_t)M_ * D_];     // attn out hi [M,D]
__device__ __nv_bfloat16 g_al[(size_t)M_ * D_];     // attn out lo
__device__ __nv_bfloat16 g_qwh[(size_t)NQKV * D_];
__device__ __nv_bfloat16 g_qwl[(size_t)NQKV * D_];
__device__ __nv_bfloat16 g_pwh[(size_t)D_ * D_];
__device__ __nv_bfloat16 g_pwl[(size_t)D_ * D_];
// head-separated QKV [B,H,S,64], hi/lo (Q pre-scaled by 1/8)
#define QKVE ((size_t)B_ * H_ * S_ * HD_)
__device__ __nv_bfloat16 g_qh[QKVE];
__device__ __nv_bfloat16 g_ql[QKVE];
__device__ __nv_bfloat16 g_kh[QKVE];
__device__ __nv_bfloat16 g_kl[QKVE];
__device__ __nv_bfloat16 g_vh[QKVE];
__device__ __nv_bfloat16 g_vl[QKVE];

// ---------------------------------------------------------------------------
// Helpers
// ---------------------------------------------------------------------------
__device__ __forceinline__ uint32_t smem_u32(const void* p) {
    uint32_t a;
    asm("{ .reg .u64 t; cvta.to.shared.u64 t, %1; cvt.u32.u64 %0, t; }" : "=r"(a) : "l"(p));
    return a;
}
#define CP16(dst, src) \
    asm volatile("cp.async.cg.shared.global [%0], [%1], 16;\n" :: "r"(dst), "l"(src))
#define CP_COMMIT()  asm volatile("cp.async.commit_group;\n" ::: "memory")
#define CP_WAIT1()   asm volatile("cp.async.wait_group 1;\n" ::: "memory")

#define LDSM4(R, addr) \
    asm volatile("ldmatrix.sync.aligned.m8n8.x4.shared.b16 {%0,%1,%2,%3}, [%4];" \
                 : "=r"((R)[0]), "=r"((R)[1]), "=r"((R)[2]), "=r"((R)[3]) : "r"(addr))
#define LDSM4T(R, addr) \
    asm volatile("ldmatrix.sync.aligned.m8n8.x4.trans.shared.b16 {%0,%1,%2,%3}, [%4];" \
                 : "=r"((R)[0]), "=r"((R)[1]), "=r"((R)[2]), "=r"((R)[3]) : "r"(addr))

#define MMA16816(D, A, b0v, b1v) \
    asm volatile("mma.sync.aligned.m16n8k16.row.col.f32.bf16.bf16.f32 " \
                 "{%0,%1,%2,%3},{%4,%5,%6,%7},{%8,%9},{%0,%1,%2,%3};" \
                 : "+f"((D)[0]), "+f"((D)[1]), "+f"((D)[2]), "+f"((D)[3]) \
                 : "r"((A)[0]), "r"((A)[1]), "r"((A)[2]), "r"((A)[3]), \
                   "r"(b0v), "r"(b1v))

__device__ __forceinline__ uint32_t pack_bf16x2(float a, float b) {
    __nv_bfloat162 v = __floats2bfloat162_rn(a, b);
    return *(uint32_t*)&v;
}

// ---------------------------------------------------------------------------
// Split fp32 -> bf16 hi/lo
// ---------------------------------------------------------------------------
__global__ __launch_bounds__(256) void split_kernel(
    const float* __restrict__ src, __nv_bfloat16* __restrict__ hi,
    __nv_bfloat16* __restrict__ lo, int n4)
{
    int i = blockIdx.x * blockDim.x + threadIdx.x;
    if (i >= n4) return;
    float4 v = ((const float4*)src)[i];
    union { __nv_bfloat16 b[4]; uint2 u; } uh, ul;
    float f[4] = {v.x, v.y, v.z, v.w};
#pragma unroll
    for (int j = 0; j < 4; j++) {
        __nv_bfloat16 h = __float2bfloat16_rn(f[j]);
        uh.b[j] = h;
        ul.b[j] = __float2bfloat16_rn(f[j] - __bfloat162float(h));
    }
    ((uint2*)hi)[i] = uh.u;
    ((uint2*)lo)[i] = ul.u;
}

// ---------------------------------------------------------------------------
// bf16x3 tensor-core GEMM: C = (Ah+Al)@(Wh+Wl)^T + bias
// MODE 0: plain fp32 C store.   MODE 1: QKV split-store to head-sep arrays.
// ---------------------------------------------------------------------------
#define KT        32
#define RSTRIDE   80
#define TILE_B    (128 * RSTRIDE)
#define STAGE_B   (4 * TILE_B)
#define NSTAGE    3
#define GEMM_SMEM (NSTAGE * STAGE_B)

template<int MODE>
__global__ __launch_bounds__(256, 1) void gemm_mma_kernel(
    const __nv_bfloat16* __restrict__ Ah, const __nv_bfloat16* __restrict__ Al,
    const __nv_bfloat16* __restrict__ Wh, const __nv_bfloat16* __restrict__ Wl,
    const float* __restrict__ bias, float* __restrict__ C, int N, int K,
    __nv_bfloat16* __restrict__ oqh, __nv_bfloat16* __restrict__ oql,
    __nv_bfloat16* __restrict__ okh, __nv_bfloat16* __restrict__ okl,
    __nv_bfloat16* __restrict__ ovh, __nv_bfloat16* __restrict__ ovl)
{
    extern __shared__ char smem[];
    const uint32_t sb = smem_u32(smem);
    const int tid  = threadIdx.x;
    const int wid  = tid >> 5;
    const int lane = tid & 31;
    const int wm   = wid & 3;
    const int wn   = wid >> 2;
    const int m0   = blockIdx.y * 128;
    const int n0   = blockIdx.x * 128;

    float acc[2][8][4];
#pragma unroll
    for (int a = 0; a < 2; a++)
#pragma unroll
        for (int b = 0; b < 8; b++)
#pragma unroll
            for (int c = 0; c < 4; c++) acc[a][b][c] = 0.f;

    const int nkc = K / KT;

    auto issue_stage = [&](int kc, int s) {
        const int k0 = kc * KT;
        const uint32_t sbase = sb + s * STAGE_B;
#pragma unroll
        for (int it = 0; it < 8; it++) {
            const int lin  = it * 256 + tid;
            const int tile = lin >> 9;
            const int idx  = lin & 511;
            const int r    = idx >> 2;
            const int c    = idx & 3;
            const uint32_t dst = sbase + tile * TILE_B + r * RSTRIDE + c * 16;
            const __nv_bfloat16* src;
            if (tile == 0)      src = Ah + (size_t)(m0 + r) * K + k0 + c * 8;
            else if (tile == 1) src = Al + (size_t)(m0 + r) * K + k0 + c * 8;
            else if (tile == 2) src = Wh + (size_t)(n0 + r) * K + k0 + c * 8;
            else                src = Wl + (size_t)(n0 + r) * K + k0 + c * 8;
            CP16(dst, src);
        }
        CP_COMMIT();
    };

    issue_stage(0, 0);
    if (nkc > 1) issue_stage(1, 1); else CP_COMMIT();

    const int arow_base = wm * 32 + (lane & 15);
    const int aco       = (lane >> 4);
    const int brow_base = wn * 64 + (((lane >> 4) << 3) | (lane & 7));
    const int bco       = ((lane >> 3) & 1);

    for (int kc = 0; kc < nkc; kc++) {
        const int s = kc % NSTAGE;
        CP_WAIT1();
        __syncthreads();
        if (kc + 2 < nkc) issue_stage(kc + 2, (kc + 2) % NSTAGE);
        else CP_COMMIT();

        const uint32_t sbase = sb + s * STAGE_B;
#pragma unroll
        for (int j = 0; j < 2; j++) {
            uint32_t ah[2][4], al[2][4], bh[4][4], bl[4][4];
#pragma unroll
            for (int mt = 0; mt < 2; mt++) {
                const uint32_t ad = sbase + (arow_base + mt * 16) * RSTRIDE
                                  + (2 * j + aco) * 16;
                LDSM4(ah[mt], ad);
                LDSM4(al[mt], ad + TILE_B);
            }
#pragma unroll
            for (int ng = 0; ng < 4; ng++) {
                const uint32_t bd = sbase + 2 * TILE_B
                                  + (brow_base + ng * 16) * RSTRIDE
                                  + (2 * j + bco) * 16;
                LDSM4(bh[ng], bd);
                LDSM4(bl[ng], bd + TILE_B);
            }
#pragma unroll
            for (int mt = 0; mt < 2; mt++)
#pragma unroll
                for (int ng = 0; ng < 4; ng++)
#pragma unroll
                    for (int p = 0; p < 2; p++) {
                        float* d = acc[mt][ng * 2 + p];
                        MMA16816(d, ah[mt], bh[ng][2 * p], bh[ng][2 * p + 1]);
                        MMA16816(d, ah[mt], bl[ng][2 * p], bl[ng][2 * p + 1]);
                        MMA16816(d, al[mt], bh[ng][2 * p], bh[ng][2 * p + 1]);
                    }
        }
        __syncthreads();
    }

    const int g = lane >> 2;
    const int t = lane & 3;
#pragma unroll
    for (int mt = 0; mt < 2; mt++) {
        const int row0 = m0 + wm * 32 + mt * 16 + g;
#pragma unroll
        for (int nt = 0; nt < 8; nt++) {
            const int col = n0 + wn * 64 + nt * 8 + t * 2;
            const float2 bv = *(const float2*)&bias[col];
            float v00 = acc[mt][nt][0] + bv.x, v01 = acc[mt][nt][1] + bv.y;
            float v10 = acc[mt][nt][2] + bv.x, v11 = acc[mt][nt][3] + bv.y;
            if (MODE == 0) {
                *(float2*)&C[(size_t)row0 * N + col]       = make_float2(v00, v01);
                *(float2*)&C[(size_t)(row0 + 8) * N + col] = make_float2(v10, v11);
            } else {
                const int sec = col / 768;
                const int rem = col - sec * 768;
                const int h   = rem >> 6;
                const int d   = rem & 63;
                if (sec == 0) { v00 *= 0.125f; v01 *= 0.125f; v10 *= 0.125f; v11 *= 0.125f; }
                __nv_bfloat16* dh = (sec == 0) ? oqh : (sec == 1) ? okh : ovh;
                __nv_bfloat16* dl = (sec == 0) ? oql : (sec == 1) ? okl : ovl;
#pragma unroll
                for (int rr = 0; rr < 2; rr++) {
                    const int row = row0 + rr * 8;
                    const float a0 = rr ? v10 : v00, a1 = rr ? v11 : v01;
                    const int bb = row >> 9, ss = row & 511;
                    const size_t idx = (((size_t)bb * H_ + h) * S_ + ss) * HD_ + d;
                    const float h0 = __bfloat162float(__float2bfloat16_rn(a0));
                    const float h1 = __bfloat162float(__float2bfloat16_rn(a1));
                    *(uint32_t*)&dh[idx] = pack_bf16x2(a0, a1);
                    *(uint32_t*)&dl[idx] = pack_bf16x2(a0 - h0, a1 - h1);
                }
            }
        }
    }
}

// ---------------------------------------------------------------------------
// Tensor-core flash attention.
// Grid (S/128, H, B), 256 threads (8 warps x 16 q-rows). kv tiles of 64.
// Smem: Q hi/lo [128][72] + 2 stages x {Kh,Kl,Vh,Vl}[64][72]. 144B row stride.
// S = Qh Kh^T + Qh Kl^T + Ql Kh^T (Q pre-scaled); online softmax;
// O += Ph Vh + Ph Vl + Pl Vh. Output -> g_ah/g_al [M,D].
// ---------------------------------------------------------------------------
#define ARS      144                       // attn row stride bytes (72 bf16)
#define QT_B     (128 * ARS)               // 18432 per Q tile
#define AT_B     (64 * ARS)                // 9216 per kv tile
#define ASTAGE_B (4 * AT_B)                // 36864
#define ATT_SMEM (2 * QT_B + 2 * ASTAGE_B) // 110592

__global__ __launch_bounds__(256, 2) void attn_tc_kernel()
{
    extern __shared__ char smem[];
    const uint32_t sb = smem_u32(smem);
    const uint32_t QH = sb, QL = sb + QT_B;
    const int tid  = threadIdx.x;
    const int wid  = tid >> 5;
    const int lane = tid & 31;
    const int g    = lane >> 2;
    const int t    = lane & 3;

    const int qt = blockIdx.x;   // 0..3
    const int h  = blockIdx.y;
    const int b  = blockIdx.z;

    const size_t headbase = ((size_t)b * H_ + h) * S_ * HD_;
    const size_t qbase    = headbase + (size_t)qt * 128 * HD_;

    // ---- load Q hi/lo (group 0) ----
#pragma unroll
    for (int it = 0; it < 8; it++) {
        const int lin  = it * 256 + tid;   // 0..2047
        const int half = lin >> 10;
        const int idx  = lin & 1023;
        const int r    = idx >> 3;
        const int c    = idx & 7;
        const uint32_t dst = (half ? QL : QH) + r * ARS + c * 16;
        const __nv_bfloat16* src = (half ? g_ql : g_qh) + qbase + (size_t)r * HD_ + c * 8;
        CP16(dst, src);
    }
    CP_COMMIT();

    auto issue_kv = [&](int kt, int s) {
        const uint32_t sbase = sb + 2 * QT_B + s * ASTAGE_B;
        const size_t kvb = headbase + (size_t)kt * 64 * HD_;
#pragma unroll
        for (int it = 0; it < 8; it++) {
            const int lin  = it * 256 + tid;  // 0..2047
            const int tile = lin >> 9;
            const int idx  = lin & 511;
            const int r    = idx >> 3;
            const int c    = idx & 7;
            const uint32_t dst = sbase + tile * AT_B + r * ARS + c * 16;
            const __nv_bfloat16* base =
                (tile == 0) ? g_kh : (tile == 1) ? g_kl : (tile == 2) ? g_vh : g_vl;
            CP16(dst, base + kvb + (size_t)r * HD_ + c * 8);
        }
        CP_COMMIT();
    };

    issue_kv(0, 0);
    issue_kv(1, 1);

    float oacc[8][4];
#pragma unroll
    for (int j = 0; j < 8; j++)
#pragma unroll
        for (int c = 0; c < 4; c++) oacc[j][c] = 0.f;
    float mrow[2] = {-1e30f, -1e30f};
    float lrow[2] = {0.f, 0.f};

    // ldmatrix lane-address components
    const int qa_row = wid * 16 + (lane & 15);       // Q/A rows
    const int qa_k   = (lane >> 4) * 8;              // Q k offset
    const int kb_row = (lane & 7) + 8 * (lane >> 4); // K: + jp*16
    const int kb_k   = ((lane >> 3) & 1) * 8;
    const int vb_row = (lane & 15);                  // V: + i*16
    const int vb_d   = (lane >> 4) * 8;              // + dv*16

    for (int kt = 0; kt < 8; kt++) {
        CP_WAIT1();
        __syncthreads();
        const uint32_t st  = sb + 2 * QT_B + (kt & 1) * ASTAGE_B;
        const uint32_t KHs = st, KLs = st + AT_B, VHs = st + 2 * AT_B, VLs = st + 3 * AT_B;

        // ---- S = Qh Kh^T + Qh Kl^T + Ql Kh^T ----
        float sacc[8][4];
#pragma unroll
        for (int j = 0; j < 8; j++)
#pragma unroll
            for (int c = 0; c < 4; c++) sacc[j][c] = 0.f;

#pragma unroll
        for (int ks = 0; ks < 4; ks++) {
            uint32_t qh[4], ql[4];
            const uint32_t qa = QH + qa_row * ARS + (ks * 16 + qa_k) * 2;
            LDSM4(qh, qa);
            LDSM4(ql, qa + QT_B);
#pragma unroll
            for (int jp = 0; jp < 4; jp++) {
                uint32_t kh[4], kl[4];
                const uint32_t ka = KHs + (jp * 16 + kb_row) * ARS + (ks * 16 + kb_k) * 2;
                LDSM4(kh, ka);
                LDSM4(kl, ka + AT_B);
                MMA16816(sacc[2 * jp],     qh, kh[0], kh[1]);
                MMA16816(sacc[2 * jp + 1], qh, kh[2], kh[3]);
                MMA16816(sacc[2 * jp],     qh, kl[0], kl[1]);
                MMA16816(sacc[2 * jp + 1], qh, kl[2], kl[3]);
                MMA16816(sacc[2 * jp],     ql, kh[0], kh[1]);
                MMA16816(sacc[2 * jp + 1], ql, kh[2], kh[3]);
            }
        }

        // ---- online softmax (rows g, g+8; quad reduce over t) ----
        float mloc0 = -1e30f, mloc1 = -1e30f;
#pragma unroll
        for (int j = 0; j < 8; j++) {
            mloc0 = fmaxf(mloc0, fmaxf(sacc[j][0], sacc[j][1]));
            mloc1 = fmaxf(mloc1, fmaxf(sacc[j][2], sacc[j][3]));
        }
        mloc0 = fmaxf(mloc0, __shfl_xor_sync(0xffffffffu, mloc0, 1));
        mloc0 = fmaxf(mloc0, __shfl_xor_sync(0xffffffffu, mloc0, 2));
        mloc1 = fmaxf(mloc1, __shfl_xor_sync(0xffffffffu, mloc1, 1));
        mloc1 = fmaxf(mloc1, __shfl_xor_sync(0xffffffffu, mloc1, 2));

        const float nm0 = fmaxf(mrow[0], mloc0);
        const float nm1 = fmaxf(mrow[1], mloc1);
        const float cr0 = __expf(mrow[0] - nm0);
        const float cr1 = __expf(mrow[1] - nm1);
        mrow[0] = nm0; mrow[1] = nm1;
        lrow[0] *= cr0; lrow[1] *= cr1;
#pragma unroll
        for (int j = 0; j < 8; j++) {
            oacc[j][0] *= cr0; oacc[j][1] *= cr0;
            oacc[j][2] *= cr1; oacc[j][3] *= cr1;
        }
        float ll0 = 0.f, ll1 = 0.f;
#pragma unroll
        for (int j = 0; j < 8; j++) {
            sacc[j][0] = __expf(sacc[j][0] - nm0);
            sacc[j][1] = __expf(sacc[j][1] - nm0);
            sacc[j][2] = __expf(sacc[j][2] - nm1);
            sacc[j][3] = __expf(sacc[j][3] - nm1);
            ll0 += sacc[j][0] + sacc[j][1];
            ll1 += sacc[j][2] + sacc[j][3];
        }
        ll0 += __shfl_xor_sync(0xffffffffu, ll0, 1);
        ll0 += __shfl_xor_sync(0xffffffffu, ll0, 2);
        ll1 += __shfl_xor_sync(0xffffffffu, ll1, 1);
        ll1 += __shfl_xor_sync(0xffffffffu, ll1, 2);
        lrow[0] += ll0; lrow[1] += ll1;

        // ---- O += Ph Vh + Ph Vl + Pl Vh ----
#pragma unroll
        for (int i = 0; i < 4; i++) {
            uint32_t pah[4], pal[4];
#pragma unroll
            for (int hf = 0; hf < 2; hf++) {       // frag 2i, 2i+1
                const float* sp = sacc[2 * i + hf];
                float h0 = __bfloat162float(__float2bfloat16_rn(sp[0]));
                float h1 = __bfloat162float(__float2bfloat16_rn(sp[1]));
                float h2 = __bfloat162float(__float2bfloat16_rn(sp[2]));
                float h3 = __bfloat162float(__float2bfloat16_rn(sp[3]));
                pah[2 * hf]     = pack_bf16x2(sp[0], sp[1]);
                pah[2 * hf + 1] = pack_bf16x2(sp[2], sp[3]);
                pal[2 * hf]     = pack_bf16x2(sp[0] - h0, sp[1] - h1);
                pal[2 * hf + 1] = pack_bf16x2(sp[2] - h2, sp[3] - h3);
            }
            // reorder to A-frag convention: a0=(g,k lo),a1=(g+8,k lo),a2=(g,k hi),a3=(g+8,k hi)
            uint32_t Ah4[4] = {pah[0], pah[1], pah[2], pah[3]};
            uint32_t Al4[4] = {pal[0], pal[1], pal[2], pal[3]};
#pragma unroll
            for (int dv = 0; dv < 4; dv++) {
                uint32_t vh[4], vl[4];
                const uint32_t va = VHs + (i * 16 + vb_row) * ARS + (dv * 16 + vb_d) * 2;
                LDSM4T(vh, va);
                LDSM4T(vl, va + AT_B);
                MMA16816(oacc[2 * dv],     Ah4, vh[0], vh[1]);
                MMA16816(oacc[2 * dv + 1], Ah4, vh[2], vh[3]);
                MMA16816(oacc[2 * dv],     Ah4, vl[0], vl[1]);
                MMA16816(oacc[2 * dv + 1], Ah4, vl[2], vl[3]);
                MMA16816(oacc[2 * dv],     Al4, vh[0], vh[1]);
                MMA16816(oacc[2 * dv + 1], Al4, vh[2], vh[3]);
            }
        }

        __syncthreads();
        if (kt + 2 < 8) issue_kv(kt + 2, kt & 1);
    }

    // ---- epilogue: normalize, split hi/lo, store to [M,D] ----
    const float inv0 = 1.f / lrow[0];
    const float inv1 = 1.f / lrow[1];
    const int s0 = qt * 128 + wid * 16 + g;
#pragma unroll
    for (int rr = 0; rr < 2; rr++) {
        const int srow = s0 + rr * 8;
        const float inv = rr ? inv1 : inv0;
        const size_t obase = ((size_t)b * S_ + srow) * D_ + h * HD_;
#pragma unroll
        for (int j = 0; j < 8; j++) {
            const int d = j * 8 + t * 2;
            const float a0 = oacc[j][2 * rr]     * inv;
            const float a1 = oacc[j][2 * rr + 1] * inv;
            const float h0 = __bfloat162float(__float2bfloat16_rn(a0));
            const float h1 = __bfloat162float(__float2bfloat16_rn(a1));
            *(uint32_t*)&g_ah[obase + d] = pack_bf16x2(a0, a1);
            *(uint32_t*)&g_al[obase + d] = pack_bf16x2(a0 - h0, a1 - h1);
        }
    }
}

// ---------------------------------------------------------------------------
extern "C" void kernel_launch(void* const* d_in, const int* in_sizes, int n_in,
                              void* d_out, int out_size)
{
    const float* x      = (const float*)d_in[0];
    const float* qkv_w  = (const float*)d_in[1];
    const float* qkv_b  = (const float*)d_in[2];
    const float* proj_w = (const float*)d_in[3];
    const float* proj_b = (const float*)d_in[4];
    float* out = (float*)d_out;

    __nv_bfloat16 *xh, *xl, *ah, *al, *qwh, *qwl, *pwh, *pwl;
    __nv_bfloat16 *qh, *ql, *kh, *kl, *vh, *vl;
    cudaGetSymbolAddress((void**)&xh, g_xh);
    cudaGetSymbolAddress((void**)&xl, g_xl);
    cudaGetSymbolAddress((void**)&ah, g_ah);
    cudaGetSymbolAddress((void**)&al, g_al);
    cudaGetSymbolAddress((void**)&qwh, g_qwh);
    cudaGetSymbolAddress((void**)&qwl, g_qwl);
    cudaGetSymbolAddress((void**)&pwh, g_pwh);
    cudaGetSymbolAddress((void**)&pwl, g_pwl);
    cudaGetSymbolAddress((void**)&qh, g_qh);
    cudaGetSymbolAddress((void**)&ql, g_ql);
    cudaGetSymbolAddress((void**)&kh, g_kh);
    cudaGetSymbolAddress((void**)&kl, g_kl);
    cudaGetSymbolAddress((void**)&vh, g_vh);
    cudaGetSymbolAddress((void**)&vl, g_vl);

    cudaFuncSetAttribute(gemm_mma_kernel<0>,
                         cudaFuncAttributeMaxDynamicSharedMemorySize, GEMM_SMEM);
    cudaFuncSetAttribute(gemm_mma_kernel<1>,
                         cudaFuncAttributeMaxDynamicSharedMemorySize, GEMM_SMEM);
    cudaFuncSetAttribute(attn_tc_kernel,
                         cudaFuncAttributeMaxDynamicSharedMemorySize, ATT_SMEM);

    // 1) splits
    {
        int n4 = (M_ * D_) / 4;
        split_kernel<<<(n4 + 255) / 256, 256>>>(x, xh, xl, n4);
        n4 = (NQKV * D_) / 4;
        split_kernel<<<(n4 + 255) / 256, 256>>>(qkv_w, qwh, qwl, n4);
        n4 = (D_ * D_) / 4;
        split_kernel<<<(n4 + 255) / 256, 256>>>(proj_w, pwh, pwl, n4);
    }

    // 2) QKV projection -> head-separated bf16 hi/lo (Q pre-scaled)
    {
        dim3 g(NQKV / 128, M_ / 128);
        gemm_mma_kernel<1><<<g, 256, GEMM_SMEM>>>(xh, xl, qwh, qwl, qkv_b,
                                                  nullptr, NQKV, D_,
                                                  qh, ql, kh, kl, vh, vl);
    }

    // 3) tensor-core flash attention -> g_ah/g_al
    {
        dim3 g(S_ / 128, H_, B_);
        attn_tc_kernel<<<g, 256, ATT_SMEM>>>();
    }

    // 4) output projection
    {
        dim3 g(D_ / 128, M_ / 128);
        gemm_mma_kernel<0><<<g, 256, GEMM_SMEM>>>(ah, al, pwh, pwl, proj_b, out,
                                                  D_, D_,
                                                  nullptr, nullptr, nullptr,
                                                  nullptr, nullptr, nullptr);
    }
}